// round 12
// baseline (speedup 1.0000x reference)
#include <cuda_runtime.h>
#include <math.h>
#include <stdint.h>

#define LSEQ 2048
#define HD   512
#define BSZ  16

// ------------- device scratch (static; no runtime allocation) -------------
__device__ __align__(16) float d_P [11 * 4096];
__device__ __align__(16) float d_PT[11 * 4096];
__device__ __align__(16) float d_Bbar[64];
__device__ __align__(16) float d_W0 [64 * 64];
__device__ __align__(16) float d_Vr0[64 * 64];
__device__ __align__(16) float d_W[LSEQ * 64];    // w[s][n]
__device__ __align__(16) float d_V[LSEQ * 64];    // v[t][n] = C Abar^{L-1-t}

// =============== packed f32x2 helpers ===============
__device__ __forceinline__ uint64_t dup2(float x) {
    uint64_t r; uint32_t u = __float_as_uint(x);
    asm("mov.b64 %0, {%1, %1};" : "=l"(r) : "r"(u));
    return r;
}
__device__ __forceinline__ void fma2(uint64_t& d, uint64_t a, uint64_t b) {
    asm("fma.rn.f32x2 %0, %1, %2, %0;" : "+l"(d) : "l"(a), "l"(b));
}
__device__ __forceinline__ void add2(uint64_t& d, uint64_t a) {
    asm("add.rn.f32x2 %0, %0, %1;" : "+l"(d) : "l"(a));
}
__device__ __forceinline__ void cpa16(uint32_t dst, const void* src) {
    asm volatile("cp.async.ca.shared.global [%0], [%1], 16;"
                 :: "r"(dst), "l"(__cvta_generic_to_global(src)));
}
__device__ __forceinline__ void cpa_commit() {
    asm volatile("cp.async.commit_group;");
}
__device__ __forceinline__ void cpa_wait0() {
    asm volatile("cp.async.wait_group 0;" ::: "memory");
}

// =============== setup (R10 version): fp32 4x4 matmul, transposed copies ===============
__device__ __forceinline__ void mm64T(const float* __restrict__ AT, const float* __restrict__ B,
                                      float* __restrict__ C, float* __restrict__ CT,
                                      int tid, int mode, float scale) {
    int tx = tid & 15, ty = tid >> 4;
    int j0 = tx << 2, i0 = ty << 2;
    float acc[4][4];
#pragma unroll
    for (int a = 0; a < 4; a++)
#pragma unroll
        for (int q = 0; q < 4; q++) acc[a][q] = 0.f;
#pragma unroll 8
    for (int k = 0; k < 64; k++) {
        float4 av = *(const float4*)(AT + k * 64 + i0);
        float4 bv = *(const float4*)(B  + k * 64 + j0);
#pragma unroll
        for (int a = 0; a < 4; a++) {
            float aa = (&av.x)[a];
            acc[a][0] = fmaf(aa, bv.x, acc[a][0]);
            acc[a][1] = fmaf(aa, bv.y, acc[a][1]);
            acc[a][2] = fmaf(aa, bv.z, acc[a][2]);
            acc[a][3] = fmaf(aa, bv.w, acc[a][3]);
        }
    }
#pragma unroll
    for (int a = 0; a < 4; a++) {
        float4 o;
#pragma unroll
        for (int q = 0; q < 4; q++) {
            float v = acc[a][q];
            if (mode == 1) v = v * scale + ((i0 + a) == (j0 + q) ? 1.f : 0.f);
            (&o.x)[q] = v;
        }
        *(float4*)(C + (i0 + a) * 64 + j0) = o;
    }
#pragma unroll
    for (int q = 0; q < 4; q++) {
        float4 o;
#pragma unroll
        for (int a = 0; a < 4; a++) {
            float v = acc[a][q];
            if (mode == 1) v = v * scale + ((i0 + a) == (j0 + q) ? 1.f : 0.f);
            (&o.x)[a] = v;
        }
        *(float4*)(CT + (j0 + q) * 64 + i0) = o;
    }
}

__global__ void __launch_bounds__(256, 1)
setup_kernel(const float* __restrict__ B_in, const float* __restrict__ logdt) {
    extern __shared__ float sm[];
    float* As  = sm;
    float* Xs  = sm + 4096;
    float* XsT = sm + 8192;
    float* R0  = sm + 12288;
    float* R0T = sm + 16384;
    float* R1  = sm + 20480;
    float* R1T = sm + 24576;
    __shared__ float colsum[64], rhs[64], bbsh[64], bsh[64];
    __shared__ int s_sh;
    int tid = threadIdx.x;

    double dt = exp((double)logdt[0]);
    for (int e = tid; e < 4096; e += 256) {
        int i = e >> 6, j = e & 63;
        float a = 0.f, x = 0.f;
        if (j <= i) {
            double pij = sqrt((1.0 + 2.0 * i) * (1.0 + 2.0 * j));
            double av = pij - (i == j ? (double)i : 0.0);
            a = (float)(-av);
            x = (float)(-av * dt);
        }
        As[e] = a; Xs[e] = x;
        XsT[(j << 6) + i] = x;
    }
    if (tid < 64) bsh[tid] = B_in[tid];
    __syncthreads();
    if (tid < 64) {
        float ssum = 0.f;
        for (int i = tid; i < 64; i++) ssum += fabsf(Xs[i * 64 + tid]);
        colsum[tid] = ssum;
    }
    __syncthreads();
    if (tid == 0) {
        float mx = 0.f;
        for (int j = 0; j < 64; j++) mx = fmaxf(mx, colsum[j]);
        int s = 0; float v = mx;
        while (v > 1.0f && s < 30) { v *= 0.5f; s++; }
        s_sh = s;
    }
    __syncthreads();
    int s = s_sh;
    float scale = ldexpf(1.0f, -s);
    for (int e = tid; e < 4096; e += 256) { Xs[e] *= scale; XsT[e] *= scale; }
    __syncthreads();

    for (int e = tid; e < 4096; e += 256) {
        int i = e >> 6, j = e & 63;
        float d = (i == j) ? 1.f : 0.f;
        R0[e]  = Xs[e]  * (1.f / 12.f) + d;
        R0T[e] = XsT[e] * (1.f / 12.f) + d;
    }
    __syncthreads();
    float *cur = R0, *curT = R0T, *nxt = R1, *nxtT = R1T;
    for (int k = 11; k >= 1; k--) {
        mm64T(XsT, cur, nxt, nxtT, tid, 1, 1.f / (float)k);
        __syncthreads();
        float* t;
        t = cur; cur = nxt; nxt = t;
        t = curT; curT = nxtT; nxtT = t;
    }
    for (int q = 0; q < s; q++) {
        mm64T(curT, cur, nxt, nxtT, tid, 0, 0.f);
        __syncthreads();
        float* t;
        t = cur; cur = nxt; nxt = t;
        t = curT; curT = nxtT; nxtT = t;
    }
    if (tid < 64) {
        float acc = 0.f;
        for (int j = 0; j < 64; j++) {
            float p = cur[tid * 64 + j] - (tid == j ? 1.f : 0.f);
            acc = fmaf(p, bsh[j], acc);
        }
        rhs[tid] = acc;
    }
    __syncthreads();
    for (int e = tid; e < 4096; e += 256) { d_P[e] = cur[e]; d_PT[e] = curT[e]; }
    for (int k = 1; k < 11; k++) {
        mm64T(curT, cur, nxt, nxtT, tid, 0, 0.f);
        __syncthreads();
        for (int e = tid; e < 4096; e += 256) {
            d_P [k * 4096 + e] = nxt[e];
            d_PT[k * 4096 + e] = nxtT[e];
        }
        float* t;
        t = cur; cur = nxt; nxt = t;
        t = curT; curT = nxtT; nxtT = t;
        __syncthreads();
    }
    float accv = (tid < 64) ? rhs[tid] : 0.f;
    for (int j = 0; j < 64; j++) {
        if (tid == j) bbsh[j] = accv / As[j * 64 + j];
        __syncthreads();
        if (tid < 64 && tid > j) accv = fmaf(-As[tid * 64 + j], bbsh[j], accv);
        __syncthreads();
    }
    if (tid < 64) d_Bbar[tid] = bbsh[tid];
}

// =============== stage A: Krylov doubling for first 64 w / vrev ===============
__global__ void __launch_bounds__(256, 1)
stageA_kernel(const float* __restrict__ C_in) {
    __shared__ float M[4096];
    __shared__ float Pb[4096];
    int tid = threadIdx.x;
    int isW = (blockIdx.x == 0);
    if (tid < 64) M[tid] = isW ? d_Bbar[tid] : C_in[tid];
    for (int k = 0; k < 6; k++) {
        const float* src = (isW ? d_PT : d_P) + k * 4096;
        __syncthreads();
        for (int f = tid; f < 1024; f += 256)
            ((float4*)Pb)[f] = __ldg((const float4*)src + f);
        __syncthreads();
        int half = 1 << k;
        for (int idx = tid; idx < half * 16; idx += 256) {
            int row = idx >> 4, n0 = (idx & 15) << 2;
            float4 acc = make_float4(0.f, 0.f, 0.f, 0.f);
            for (int m = 0; m < 64; m++) {
                float w = M[row * 64 + m];
                float4 p = *(const float4*)(Pb + m * 64 + n0);
                acc.x = fmaf(w, p.x, acc.x);
                acc.y = fmaf(w, p.y, acc.y);
                acc.z = fmaf(w, p.z, acc.z);
                acc.w = fmaf(w, p.w, acc.w);
            }
            *(float4*)(M + (half + row) * 64 + n0) = acc;
        }
    }
    __syncthreads();
    float* dst = isW ? d_W0 : d_Vr0;
    for (int f = tid; f < 1024; f += 256) ((float4*)dst)[f] = ((const float4*)M)[f];
}

// =============== chunk kernel ===============
__device__ __forceinline__ void mmg(const float* __restrict__ A, const float* __restrict__ B,
                                    float* __restrict__ out, int row0, int rowstep, int tid) {
    int tx = tid & 15, ty = tid >> 4;
    int j0 = tx << 2, i0 = ty << 2;
    float acc[4][4];
#pragma unroll
    for (int a = 0; a < 4; a++)
#pragma unroll
        for (int q = 0; q < 4; q++) acc[a][q] = 0.f;
#pragma unroll 8
    for (int k = 0; k < 64; k++) {
        float a0 = A[(i0 + 0) * 64 + k];
        float a1 = A[(i0 + 1) * 64 + k];
        float a2 = A[(i0 + 2) * 64 + k];
        float a3 = A[(i0 + 3) * 64 + k];
        float4 bv = *(const float4*)(B + k * 64 + j0);
        acc[0][0] = fmaf(a0, bv.x, acc[0][0]); acc[0][1] = fmaf(a0, bv.y, acc[0][1]);
        acc[0][2] = fmaf(a0, bv.z, acc[0][2]); acc[0][3] = fmaf(a0, bv.w, acc[0][3]);
        acc[1][0] = fmaf(a1, bv.x, acc[1][0]); acc[1][1] = fmaf(a1, bv.y, acc[1][1]);
        acc[1][2] = fmaf(a1, bv.z, acc[1][2]); acc[1][3] = fmaf(a1, bv.w, acc[1][3]);
        acc[2][0] = fmaf(a2, bv.x, acc[2][0]); acc[2][1] = fmaf(a2, bv.y, acc[2][1]);
        acc[2][2] = fmaf(a2, bv.z, acc[2][2]); acc[2][3] = fmaf(a2, bv.w, acc[2][3]);
        acc[3][0] = fmaf(a3, bv.x, acc[3][0]); acc[3][1] = fmaf(a3, bv.y, acc[3][1]);
        acc[3][2] = fmaf(a3, bv.z, acc[3][2]); acc[3][3] = fmaf(a3, bv.w, acc[3][3]);
    }
#pragma unroll
    for (int a = 0; a < 4; a++) {
        float4 o; o.x = acc[a][0]; o.y = acc[a][1]; o.z = acc[a][2]; o.w = acc[a][3];
        *(float4*)(out + (size_t)(row0 + rowstep * (i0 + a)) * 64 + j0) = o;
    }
}

__global__ void __launch_bounds__(256, 1)
chunk_kernel() {
    extern __shared__ float cs[];
    float* W0s  = cs;
    float* Vr0s = cs + 4096;
    float* Qa   = cs + 8192;
    float* Qb   = cs + 12288;
    float* QT   = cs + 16384;
    float* Pb   = cs + 20480;
    int tid = threadIdx.x;
    int c = blockIdx.x;

    for (int f = tid; f < 1024; f += 256) {
        ((float4*)W0s)[f]  = __ldg((const float4*)d_W0 + f);
        ((float4*)Vr0s)[f] = __ldg((const float4*)d_Vr0 + f);
    }
    __syncthreads();

    if (c == 0) {
        for (int f = tid; f < 1024; f += 256) ((float4*)d_W)[f] = ((const float4*)W0s)[f];
        for (int e = tid; e < 4096; e += 256) {
            int r = e >> 6, n = e & 63;
            d_V[(size_t)(2047 - r) * 64 + n] = Vr0s[e];
        }
        return;
    }

    int bits = c;
    int k0 = __ffs(bits) - 1; bits &= bits - 1;
    for (int f = tid; f < 1024; f += 256)
        ((float4*)Qa)[f] = __ldg((const float4*)(d_P + (6 + k0) * 4096) + f);
    float *qcur = Qa, *qnxt = Qb;
    while (bits) {
        int k = __ffs(bits) - 1; bits &= bits - 1;
        __syncthreads();
        for (int f = tid; f < 1024; f += 256)
            ((float4*)Pb)[f] = __ldg((const float4*)(d_P + (6 + k) * 4096) + f);
        __syncthreads();
        mmg(qcur, Pb, qnxt, 0, 1, tid);
        float* t = qcur; qcur = qnxt; qnxt = t;
    }
    __syncthreads();
    for (int e = tid; e < 4096; e += 256) {
        int i = e >> 6, j = e & 63;
        QT[j * 64 + i] = qcur[e];
    }
    __syncthreads();
    mmg(W0s, QT, d_W, 64 * c, 1, tid);
    mmg(Vr0s, qcur, d_V, 2047 - 64 * c, -1, tid);
}

// =============== main fused chunked-scan kernel ===============
// R10 structure (512 threads, 4 roles x 128, 8r x 4h tiles, two barriers/chunk),
// with A-operands stored PRE-DUPLICATED in smem: [row][2k]=[row][2k+1]=a, so
// LDS.128 yields two packed (a,a) f32x2 operands and the hot loop has ZERO MOVs.
//   role 0: YA = V*Xcur  (K=64)            -> Yb (smem)
//   role 1: YB = Tz*U + D*U (K=64)         -> regs; post-barrier y = YA+YB -> gmem
//   role 2: Xnxt = Xcur + sum_{j<32}  W^T U -> Xnxt
//   role 3: partial sum_{j>=32} W^T U -> regs; post-barrier Xnxt += partial
// U double-buffered via cp.async; W/V single dup-buffers re-staged (reg prefetch
// + STS-expand) after the first barrier of each chunk.
__device__ __forceinline__ void g8x4d(uint64_t acc[8][2], const float* __restrict__ A,
                                      const float* __restrict__ B, int k, int r0, int h0) {
    const float* ar = A + k * 128 + (r0 << 1);
    ulonglong2 a01 = *(const ulonglong2*)ar;
    ulonglong2 a23 = *(const ulonglong2*)(ar + 4);
    ulonglong2 a45 = *(const ulonglong2*)(ar + 8);
    ulonglong2 a67 = *(const ulonglong2*)(ar + 12);
    ulonglong2 bv  = *(const ulonglong2*)(B + k * 64 + h0);
    fma2(acc[0][0], a01.x, bv.x); fma2(acc[0][1], a01.x, bv.y);
    fma2(acc[1][0], a01.y, bv.x); fma2(acc[1][1], a01.y, bv.y);
    fma2(acc[2][0], a23.x, bv.x); fma2(acc[2][1], a23.x, bv.y);
    fma2(acc[3][0], a23.y, bv.x); fma2(acc[3][1], a23.y, bv.y);
    fma2(acc[4][0], a45.x, bv.x); fma2(acc[4][1], a45.x, bv.y);
    fma2(acc[5][0], a45.y, bv.x); fma2(acc[5][1], a45.y, bv.y);
    fma2(acc[6][0], a67.x, bv.x); fma2(acc[6][1], a67.x, bv.y);
    fma2(acc[7][0], a67.y, bv.x); fma2(acc[7][1], a67.y, bv.y);
}
__device__ __forceinline__ void sts_dup4(float* p, float4 v) {
    *(float4*)p       = make_float4(v.x, v.x, v.y, v.y);
    *(float4*)(p + 4) = make_float4(v.z, v.z, v.w, v.w);
}

__global__ void __launch_bounds__(512, 1)
main_kernel(const float* __restrict__ u, const float* __restrict__ Dp, float* __restrict__ y) {
    extern __shared__ float sm[];
    float* Us0 = sm;            // [64][64] u tile (normal layout)
    float* Us1 = sm + 4096;
    float* Wd  = sm + 8192;     // [64 j][128] dup: Wd[j][2n(+1)] = W[tb+j][n]
    float* Vd  = sm + 16384;    // [64 n][128] dup: Vd[n][2i(+1)] = V[tb+i][n]
    float* Tzd = sm + 24576;    // [64 j][128] dup: Tzd[j][2i(+1)] = Tz[j][i]
    float* Xb0 = sm + 32768;    // [64 n][64 h] state ping
    float* Xb1 = sm + 36864;    // pong
    float* Yb_ = sm + 40960;    // [64][64] Y partial

    int tid = threadIdx.x;
    int b = blockIdx.x >> 3;
    int habs = (blockIdx.x & 7) << 6;
    float Dv = Dp[0];
    uint64_t dv2 = dup2(Dv);

    uint32_t smem_u32 = (uint32_t)__cvta_generic_to_shared(sm);

    int role = tid >> 7;          // 0..3
    int t7 = tid & 127;
    int r0 = (t7 >> 4) << 3;      // i/n tile base: 0,8,...,56
    int h0 = (t7 & 15) << 2;      // h base: 0,4,...,60

    // staging coords
    int wj = tid >> 3, wq = (tid & 7) << 3;   // W: row wj, cols wq..wq+8
    int vii = tid & 63, vng = tid >> 6;       // V: row (tb+vii), n0v..n0v+8
    int n0v = vng << 3;

    const float* ub = u + (size_t)b * LSEQ * HD + habs;
    float*       yb = y + (size_t)b * LSEQ * HD + habs;

    // ---- zero X ping, stage chunk 0 (synchronous) ----
    for (int e = tid; e < 4096; e += 512) Xb0[e] = 0.f;
    for (int f = tid; f < 1024; f += 512) {
        int j = f >> 4, q = f & 15;
        ((float4*)Us0)[(j << 4) + q] = __ldg((const float4*)(ub + (size_t)j * HD) + q);
    }
    {
        float4 w0 = __ldg((const float4*)(d_W + (size_t)wj * 64 + wq));
        float4 w1 = __ldg((const float4*)(d_W + (size_t)wj * 64 + wq + 4));
        sts_dup4(Wd + wj * 128 + (wq << 1), w0);
        sts_dup4(Wd + wj * 128 + (wq << 1) + 8, w1);
        float4 v0 = __ldg((const float4*)(d_V + (size_t)vii * 64 + n0v));
        float4 v1 = __ldg((const float4*)(d_V + (size_t)vii * 64 + n0v + 4));
#pragma unroll
        for (int k = 0; k < 4; k++) {
            float a = (&v0.x)[k];
            *(float2*)(Vd + (n0v + k) * 128 + (vii << 1)) = make_float2(a, a);
            float bq = (&v1.x)[k];
            *(float2*)(Vd + (n0v + 4 + k) * 128 + (vii << 1)) = make_float2(bq, bq);
        }
    }
    __syncthreads();

    // ---- one-time Toeplitz: Tz[j][i] = dot(v_i, w_j) masked i>=j, stored dup ----
    {
        int jj = tid >> 3;
        int i0t = (tid & 7) << 3;
        float ta[8];
#pragma unroll
        for (int q = 0; q < 8; q++) ta[q] = 0.f;
#pragma unroll 4
        for (int n = 0; n < 64; n++) {
            float w = Wd[jj * 128 + (n << 1)];
            const float* vr = Vd + n * 128 + (i0t << 1);
#pragma unroll
            for (int q2 = 0; q2 < 4; q2++) {
                float4 vv = *(const float4*)(vr + (q2 << 2));   // pairs (i,i),(i+1,i+1)
                ta[2 * q2]     = fmaf(w, vv.x, ta[2 * q2]);
                ta[2 * q2 + 1] = fmaf(w, vv.z, ta[2 * q2 + 1]);
            }
        }
#pragma unroll
        for (int q2 = 0; q2 < 4; q2++) {
            float t0 = (i0t + 2 * q2     >= jj) ? ta[2 * q2]     : 0.f;
            float t1 = (i0t + 2 * q2 + 1 >= jj) ? ta[2 * q2 + 1] : 0.f;
            *(float4*)(Tzd + jj * 128 + (i0t << 1) + (q2 << 2)) =
                make_float4(t0, t0, t1, t1);
        }
    }
    __syncthreads();

    float* Xc = Xb0;
    float* Xn = Xb1;

    for (int c = 0; c < 32; c++) {
        int p = c & 1;
        int tb = c << 6;
        const float* Uc = p ? Us1 : Us0;
        uint32_t uAlt = smem_u32 + (p ? 0u : 4096u * 4u);

        // ---- async prefetch next chunk: U via cp.async; W,V into regs ----
        float4 pw0, pw1, pv0, pv1;
        if (c < 31) {
            int tbn = tb + 64;
#pragma unroll
            for (int it = 0; it < 2; it++) {
                int f = (it << 9) + tid;
                int j = f >> 4, q = f & 15;
                cpa16(uAlt + (uint32_t)((j << 6) + (q << 2)) * 4u,
                      ub + (size_t)(tbn + j) * HD + (q << 2));
            }
            cpa_commit();
            pw0 = __ldg((const float4*)(d_W + (size_t)(tbn + wj) * 64 + wq));
            pw1 = __ldg((const float4*)(d_W + (size_t)(tbn + wj) * 64 + wq + 4));
            pv0 = __ldg((const float4*)(d_V + (size_t)(tbn + vii) * 64 + n0v));
            pv1 = __ldg((const float4*)(d_V + (size_t)(tbn + vii) * 64 + n0v + 4));
        }

        // ---- compute role partials ----
        uint64_t acc[8][2];
#pragma unroll
        for (int ai = 0; ai < 8; ai++) { acc[ai][0] = 0ull; acc[ai][1] = 0ull; }

        if (role == 0) {
#pragma unroll 4
            for (int n = 0; n < 64; n++) g8x4d(acc, Vd, Xc, n, r0, h0);
#pragma unroll
            for (int ai = 0; ai < 8; ai++) {
                ulonglong2 o; o.x = acc[ai][0]; o.y = acc[ai][1];
                *(ulonglong2*)(Yb_ + (r0 + ai) * 64 + h0) = o;
            }
        } else if (role == 1) {
#pragma unroll 4
            for (int j = 0; j < 64; j++) g8x4d(acc, Tzd, Uc, j, r0, h0);
#pragma unroll
            for (int ai = 0; ai < 8; ai++) {
                ulonglong2 uv = *(const ulonglong2*)(Uc + (r0 + ai) * 64 + h0);
                fma2(acc[ai][0], dv2, uv.x);
                fma2(acc[ai][1], dv2, uv.y);
            }
        } else if (role == 2) {
#pragma unroll 4
            for (int j = 0; j < 32; j++) g8x4d(acc, Wd, Uc, j, r0, h0);
#pragma unroll
            for (int ai = 0; ai < 8; ai++) {
                ulonglong2 xv = *(const ulonglong2*)(Xc + (r0 + ai) * 64 + h0);
                add2(acc[ai][0], xv.x);
                add2(acc[ai][1], xv.y);
                ulonglong2 o; o.x = acc[ai][0]; o.y = acc[ai][1];
                *(ulonglong2*)(Xn + (r0 + ai) * 64 + h0) = o;
            }
        } else {
#pragma unroll 4
            for (int j = 32; j < 64; j++) g8x4d(acc, Wd, Uc, j, r0, h0);
        }
        __syncthreads();   // B: Yb/Xn(partial) visible; all Wd/Vd/Tzd/Xc/Uc reads done

        if (role == 1) {
#pragma unroll
            for (int ai = 0; ai < 8; ai++) {
                ulonglong2 p1 = *(const ulonglong2*)(Yb_ + (r0 + ai) * 64 + h0);
                add2(acc[ai][0], p1.x);
                add2(acc[ai][1], p1.y);
                ulonglong2 o; o.x = acc[ai][0]; o.y = acc[ai][1];
                *(ulonglong2*)(yb + (size_t)(tb + r0 + ai) * HD + h0) = o;
            }
        } else if (role == 3) {
#pragma unroll
            for (int ai = 0; ai < 8; ai++) {
                float* xrow = Xn + (r0 + ai) * 64 + h0;
                ulonglong2 xv = *(const ulonglong2*)xrow;
                add2(acc[ai][0], xv.x);
                add2(acc[ai][1], xv.y);
                ulonglong2 o; o.x = acc[ai][0]; o.y = acc[ai][1];
                *(ulonglong2*)xrow = o;
            }
        }

        // ---- STS-expand next chunk's W/V into dup buffers (overwrite-safe) ----
        if (c < 31) {
            sts_dup4(Wd + wj * 128 + (wq << 1), pw0);
            sts_dup4(Wd + wj * 128 + (wq << 1) + 8, pw1);
#pragma unroll
            for (int k = 0; k < 4; k++) {
                float a = (&pv0.x)[k];
                *(float2*)(Vd + (n0v + k) * 128 + (vii << 1)) = make_float2(a, a);
                float bq = (&pv1.x)[k];
                *(float2*)(Vd + (n0v + 4 + k) * 128 + (vii << 1)) = make_float2(bq, bq);
            }
            cpa_wait0();
        }
        __syncthreads();   // D: Xn final, new W/V/U tiles visible

        float* t = Xc; Xc = Xn; Xn = t;
    }
}

extern "C" void kernel_launch(void* const* d_in, const int* in_sizes, int n_in,
                              void* d_out, int out_size) {
    const float* u      = (const float*)d_in[0];
    const float* B_ssm  = (const float*)d_in[1];
    const float* C_ssm  = (const float*)d_in[2];
    const float* D_skip = (const float*)d_in[3];
    const float* log_dt = (const float*)d_in[4];
    float* y = (float*)d_out;

    cudaFuncSetAttribute(setup_kernel, cudaFuncAttributeMaxDynamicSharedMemorySize, 114688);
    cudaFuncSetAttribute(chunk_kernel, cudaFuncAttributeMaxDynamicSharedMemorySize, 98304);
    cudaFuncSetAttribute(main_kernel,  cudaFuncAttributeMaxDynamicSharedMemorySize, 180224);

    setup_kernel<<<1, 256, 114688>>>(B_ssm, log_dt);
    stageA_kernel<<<2, 256>>>(C_ssm);
    chunk_kernel<<<32, 256, 98304>>>();
    main_kernel<<<BSZ * 8, 512, 180224>>>(u, D_skip, y);
}

// round 13
// speedup vs baseline: 1.2423x; 1.2423x over previous
#include <cuda_runtime.h>
#include <math.h>
#include <stdint.h>

#define LSEQ 2048
#define HD   512
#define BSZ  16

// ------------- device scratch (static; no runtime allocation) -------------
__device__ __align__(16) float d_P [11 * 4096];
__device__ __align__(16) float d_PT[11 * 4096];
__device__ __align__(16) float d_Bbar[64];
__device__ __align__(16) float d_W0 [64 * 64];
__device__ __align__(16) float d_Vr0[64 * 64];
__device__ __align__(16) float d_W[LSEQ * 64];    // w[s][n]
__device__ __align__(16) float d_V[LSEQ * 64];    // v[t][n] = C Abar^{L-1-t}

// =============== packed f32x2 helpers ===============
__device__ __forceinline__ uint64_t dup2(float x) {
    uint64_t r; uint32_t u = __float_as_uint(x);
    asm("mov.b64 %0, {%1, %1};" : "=l"(r) : "r"(u));
    return r;
}
__device__ __forceinline__ void fma2(uint64_t& d, uint64_t a, uint64_t b) {
    asm("fma.rn.f32x2 %0, %1, %2, %0;" : "+l"(d) : "l"(a), "l"(b));
}
__device__ __forceinline__ void add2(uint64_t& d, uint64_t a) {
    asm("add.rn.f32x2 %0, %0, %1;" : "+l"(d) : "l"(a));
}
__device__ __forceinline__ float2 un2(uint64_t v) {
    float2 r;
    asm("mov.b64 {%0, %1}, %2;" : "=f"(r.x), "=f"(r.y) : "l"(v));
    return r;
}
__device__ __forceinline__ void cpa16(uint32_t dst, const void* src) {
    asm volatile("cp.async.ca.shared.global [%0], [%1], 16;"
                 :: "r"(dst), "l"(__cvta_generic_to_global(src)));
}
__device__ __forceinline__ void cpa_commit() {
    asm volatile("cp.async.commit_group;");
}
__device__ __forceinline__ void cpa_wait0() {
    asm volatile("cp.async.wait_group 0;" ::: "memory");
}

// =============== setup matmul: 256 threads, 4x4 tiles, f32x2 inner loop ===============
// Same thread mapping / epilogue as the proven R6-R10 mm64T; only the k-loop
// math is packed (2x fewer FFMA issue slots).
__device__ __forceinline__ void mm64T(const float* __restrict__ AT, const float* __restrict__ B,
                                      float* __restrict__ C, float* __restrict__ CT,
                                      int tid, int mode, float scale) {
    int tx = tid & 15, ty = tid >> 4;
    int j0 = tx << 2, i0 = ty << 2;
    uint64_t acc[4][2];
#pragma unroll
    for (int a = 0; a < 4; a++) { acc[a][0] = 0ull; acc[a][1] = 0ull; }
#pragma unroll 8
    for (int k = 0; k < 64; k++) {
        float4 av = *(const float4*)(AT + k * 64 + i0);
        ulonglong2 bv = *(const ulonglong2*)(B + k * 64 + j0);
#pragma unroll
        for (int a = 0; a < 4; a++) {
            uint64_t ad = dup2((&av.x)[a]);
            fma2(acc[a][0], ad, bv.x);
            fma2(acc[a][1], ad, bv.y);
        }
    }
    float o[4][4];
#pragma unroll
    for (int a = 0; a < 4; a++) {
        float2 p0 = un2(acc[a][0]);
        float2 p1 = un2(acc[a][1]);
        o[a][0] = p0.x; o[a][1] = p0.y; o[a][2] = p1.x; o[a][3] = p1.y;
        if (mode == 1) {
#pragma unroll
            for (int q = 0; q < 4; q++)
                o[a][q] = o[a][q] * scale + ((i0 + a) == (j0 + q) ? 1.f : 0.f);
        }
        float4 ov; ov.x = o[a][0]; ov.y = o[a][1]; ov.z = o[a][2]; ov.w = o[a][3];
        *(float4*)(C + (i0 + a) * 64 + j0) = ov;
    }
#pragma unroll
    for (int q = 0; q < 4; q++) {
        float4 ov; ov.x = o[0][q]; ov.y = o[1][q]; ov.z = o[2][q]; ov.w = o[3][q];
        *(float4*)(CT + (j0 + q) * 64 + i0) = ov;
    }
}

__global__ void __launch_bounds__(256, 1)
setup_kernel(const float* __restrict__ B_in, const float* __restrict__ logdt) {
    extern __shared__ float sm[];
    float* As  = sm;
    float* Xs  = sm + 4096;
    float* XsT = sm + 8192;
    float* R0  = sm + 12288;
    float* R0T = sm + 16384;
    float* R1  = sm + 20480;
    float* R1T = sm + 24576;
    __shared__ float colsum[64], rhs[64], bbsh[64], bsh[64];
    __shared__ int s_sh;
    int tid = threadIdx.x;

    double dt = exp((double)logdt[0]);
    for (int e = tid; e < 4096; e += 256) {
        int i = e >> 6, j = e & 63;
        float a = 0.f, x = 0.f;
        if (j <= i) {
            double pij = sqrt((1.0 + 2.0 * i) * (1.0 + 2.0 * j));
            double av = pij - (i == j ? (double)i : 0.0);
            a = (float)(-av);
            x = (float)(-av * dt);
        }
        As[e] = a; Xs[e] = x;
        XsT[(j << 6) + i] = x;
    }
    if (tid < 64) bsh[tid] = B_in[tid];
    __syncthreads();
    if (tid < 64) {
        float ssum = 0.f;
        for (int i = tid; i < 64; i++) ssum += fabsf(Xs[i * 64 + tid]);
        colsum[tid] = ssum;
    }
    __syncthreads();
    if (tid == 0) {
        float mx = 0.f;
        for (int j = 0; j < 64; j++) mx = fmaxf(mx, colsum[j]);
        int s = 0; float v = mx;
        while (v > 2.0f && s < 30) { v *= 0.5f; s++; }   // theta = 2 (deg-12 trunc ~1.3e-6)
        s_sh = s;
    }
    __syncthreads();
    int s = s_sh;
    float scale = ldexpf(1.0f, -s);
    for (int e = tid; e < 4096; e += 256) { Xs[e] *= scale; XsT[e] *= scale; }
    __syncthreads();

    // Taylor deg-12 Horner: R = I + X/12; for k=11..1: R = I + (X*R)/k
    for (int e = tid; e < 4096; e += 256) {
        int i = e >> 6, j = e & 63;
        float d = (i == j) ? 1.f : 0.f;
        R0[e]  = Xs[e]  * (1.f / 12.f) + d;
        R0T[e] = XsT[e] * (1.f / 12.f) + d;
    }
    __syncthreads();
    float *cur = R0, *curT = R0T, *nxt = R1, *nxtT = R1T;
    for (int k = 11; k >= 1; k--) {
        mm64T(XsT, cur, nxt, nxtT, tid, 1, 1.f / (float)k);
        __syncthreads();
        float* t;
        t = cur; cur = nxt; nxt = t;
        t = curT; curT = nxtT; nxtT = t;
    }
    for (int q = 0; q < s; q++) {
        mm64T(curT, cur, nxt, nxtT, tid, 0, 0.f);
        __syncthreads();
        float* t;
        t = cur; cur = nxt; nxt = t;
        t = curT; curT = nxtT; nxtT = t;
    }
    if (tid < 64) {
        float acc = 0.f;
        for (int j = 0; j < 64; j++) {
            float p = cur[tid * 64 + j] - (tid == j ? 1.f : 0.f);
            acc = fmaf(p, bsh[j], acc);
        }
        rhs[tid] = acc;
    }
    __syncthreads();
    for (int e = tid; e < 4096; e += 256) { d_P[e] = cur[e]; d_PT[e] = curT[e]; }
    for (int k = 1; k < 11; k++) {
        mm64T(curT, cur, nxt, nxtT, tid, 0, 0.f);
        __syncthreads();
        for (int e = tid; e < 4096; e += 256) {
            d_P [k * 4096 + e] = nxt[e];
            d_PT[k * 4096 + e] = nxtT[e];
        }
        float* t;
        t = cur; cur = nxt; nxt = t;
        t = curT; curT = nxtT; nxtT = t;
        __syncthreads();
    }
    float accv = (tid < 64) ? rhs[tid] : 0.f;
    for (int j = 0; j < 64; j++) {
        if (tid == j) bbsh[j] = accv / As[j * 64 + j];
        __syncthreads();
        if (tid < 64 && tid > j) accv = fmaf(-As[tid * 64 + j], bbsh[j], accv);
        __syncthreads();
    }
    if (tid < 64) d_Bbar[tid] = bbsh[tid];
}

// =============== stage A: Krylov doubling for first 64 w / vrev ===============
__global__ void __launch_bounds__(256, 1)
stageA_kernel(const float* __restrict__ C_in) {
    __shared__ float M[4096];
    __shared__ float Pb[4096];
    int tid = threadIdx.x;
    int isW = (blockIdx.x == 0);
    if (tid < 64) M[tid] = isW ? d_Bbar[tid] : C_in[tid];
    for (int k = 0; k < 6; k++) {
        const float* src = (isW ? d_PT : d_P) + k * 4096;
        __syncthreads();
        for (int f = tid; f < 1024; f += 256)
            ((float4*)Pb)[f] = __ldg((const float4*)src + f);
        __syncthreads();
        int half = 1 << k;
        for (int idx = tid; idx < half * 16; idx += 256) {
            int row = idx >> 4, n0 = (idx & 15) << 2;
            float4 acc = make_float4(0.f, 0.f, 0.f, 0.f);
            for (int m = 0; m < 64; m++) {
                float w = M[row * 64 + m];
                float4 p = *(const float4*)(Pb + m * 64 + n0);
                acc.x = fmaf(w, p.x, acc.x);
                acc.y = fmaf(w, p.y, acc.y);
                acc.z = fmaf(w, p.z, acc.z);
                acc.w = fmaf(w, p.w, acc.w);
            }
            *(float4*)(M + (half + row) * 64 + n0) = acc;
        }
    }
    __syncthreads();
    float* dst = isW ? d_W0 : d_Vr0;
    for (int f = tid; f < 1024; f += 256) ((float4*)dst)[f] = ((const float4*)M)[f];
}

// =============== chunk kernel ===============
__device__ __forceinline__ void mmg(const float* __restrict__ A, const float* __restrict__ B,
                                    float* __restrict__ out, int row0, int rowstep, int tid) {
    int tx = tid & 15, ty = tid >> 4;
    int j0 = tx << 2, i0 = ty << 2;
    float acc[4][4];
#pragma unroll
    for (int a = 0; a < 4; a++)
#pragma unroll
        for (int q = 0; q < 4; q++) acc[a][q] = 0.f;
#pragma unroll 8
    for (int k = 0; k < 64; k++) {
        float a0 = A[(i0 + 0) * 64 + k];
        float a1 = A[(i0 + 1) * 64 + k];
        float a2 = A[(i0 + 2) * 64 + k];
        float a3 = A[(i0 + 3) * 64 + k];
        float4 bv = *(const float4*)(B + k * 64 + j0);
        acc[0][0] = fmaf(a0, bv.x, acc[0][0]); acc[0][1] = fmaf(a0, bv.y, acc[0][1]);
        acc[0][2] = fmaf(a0, bv.z, acc[0][2]); acc[0][3] = fmaf(a0, bv.w, acc[0][3]);
        acc[1][0] = fmaf(a1, bv.x, acc[1][0]); acc[1][1] = fmaf(a1, bv.y, acc[1][1]);
        acc[1][2] = fmaf(a1, bv.z, acc[1][2]); acc[1][3] = fmaf(a1, bv.w, acc[1][3]);
        acc[2][0] = fmaf(a2, bv.x, acc[2][0]); acc[2][1] = fmaf(a2, bv.y, acc[2][1]);
        acc[2][2] = fmaf(a2, bv.z, acc[2][2]); acc[2][3] = fmaf(a2, bv.w, acc[2][3]);
        acc[3][0] = fmaf(a3, bv.x, acc[3][0]); acc[3][1] = fmaf(a3, bv.y, acc[3][1]);
        acc[3][2] = fmaf(a3, bv.z, acc[3][2]); acc[3][3] = fmaf(a3, bv.w, acc[3][3]);
    }
#pragma unroll
    for (int a = 0; a < 4; a++) {
        float4 o; o.x = acc[a][0]; o.y = acc[a][1]; o.z = acc[a][2]; o.w = acc[a][3];
        *(float4*)(out + (size_t)(row0 + rowstep * (i0 + a)) * 64 + j0) = o;
    }
}

__global__ void __launch_bounds__(256, 1)
chunk_kernel() {
    extern __shared__ float cs[];
    float* W0s  = cs;
    float* Vr0s = cs + 4096;
    float* Qa   = cs + 8192;
    float* Qb   = cs + 12288;
    float* QT   = cs + 16384;
    float* Pb   = cs + 20480;
    int tid = threadIdx.x;
    int c = blockIdx.x;

    for (int f = tid; f < 1024; f += 256) {
        ((float4*)W0s)[f]  = __ldg((const float4*)d_W0 + f);
        ((float4*)Vr0s)[f] = __ldg((const float4*)d_Vr0 + f);
    }
    __syncthreads();

    if (c == 0) {
        for (int f = tid; f < 1024; f += 256) ((float4*)d_W)[f] = ((const float4*)W0s)[f];
        for (int e = tid; e < 4096; e += 256) {
            int r = e >> 6, n = e & 63;
            d_V[(size_t)(2047 - r) * 64 + n] = Vr0s[e];
        }
        return;
    }

    int bits = c;
    int k0 = __ffs(bits) - 1; bits &= bits - 1;
    for (int f = tid; f < 1024; f += 256)
        ((float4*)Qa)[f] = __ldg((const float4*)(d_P + (6 + k0) * 4096) + f);
    float *qcur = Qa, *qnxt = Qb;
    while (bits) {
        int k = __ffs(bits) - 1; bits &= bits - 1;
        __syncthreads();
        for (int f = tid; f < 1024; f += 256)
            ((float4*)Pb)[f] = __ldg((const float4*)(d_P + (6 + k) * 4096) + f);
        __syncthreads();
        mmg(qcur, Pb, qnxt, 0, 1, tid);
        float* t = qcur; qcur = qnxt; qnxt = t;
    }
    __syncthreads();
    for (int e = tid; e < 4096; e += 256) {
        int i = e >> 6, j = e & 63;
        QT[j * 64 + i] = qcur[e];
    }
    __syncthreads();
    mmg(W0s, QT, d_W, 64 * c, 1, tid);
    mmg(Vr0s, qcur, d_V, 2047 - 64 * c, -1, tid);
}

// =============== main fused chunked-scan kernel (EXACT R10 version) ===============
// 512 threads, 4 roles x 128 threads, 8i x 4h register tiles, f32x2 math.
//   role 0: YA = V*Xcur          (K=64)  -> Yb (smem)
//   role 1: YB = Tz*U + D*U      (K=64)  -> regs; then y = YA+YB -> gmem
//   role 2: Xnxt = Xcur + sum_{j<32}  W^T U  -> Xnxt (smem)
//   role 3: partial sum_{j>=32} W^T U -> regs; then Xnxt += partial
// U/W double-buffered via cp.async; V double-buffered via reg prefetch + transposed STS.
__device__ __forceinline__ void g8x4(uint64_t acc[8][2], const float* __restrict__ A,
                                     const float* __restrict__ B, int k, int r0, int h0) {
    const float* ar = A + k * 64 + r0;
    float4 a03 = *(const float4*)ar;
    float4 a47 = *(const float4*)(ar + 4);
    ulonglong2 bv = *(const ulonglong2*)(B + k * 64 + h0);
    float av[8] = {a03.x, a03.y, a03.z, a03.w, a47.x, a47.y, a47.z, a47.w};
#pragma unroll
    for (int ai = 0; ai < 8; ai++) {
        uint64_t ad = dup2(av[ai]);
        fma2(acc[ai][0], ad, bv.x);
        fma2(acc[ai][1], ad, bv.y);
    }
}

__global__ void __launch_bounds__(512, 1)
main_kernel(const float* __restrict__ u, const float* __restrict__ Dp, float* __restrict__ y) {
    extern __shared__ float sm[];
    float* Us0 = sm;            // [64][64] u tile, buffer 0
    float* Us1 = sm + 4096;
    float* Ws0 = sm + 8192;     // [64][64] W tile
    float* Ws1 = sm + 12288;
    float* Vt0 = sm + 16384;    // [64][64] V transposed [n][i]
    float* Vt1 = sm + 20480;
    float* Tz  = sm + 24576;    // [64][64] TzT[j][i]
    float* Xb0 = sm + 28672;    // [64][64] state ping
    float* Xb1 = sm + 32768;    // [64][64] state pong
    float* Yb_ = sm + 36864;    // [64][64] Y partial

    int tid = threadIdx.x;
    int b = blockIdx.x >> 3;
    int habs = (blockIdx.x & 7) << 6;
    float Dv = Dp[0];
    uint64_t dv2 = dup2(Dv);

    uint32_t smem_u32 = (uint32_t)__cvta_generic_to_shared(sm);

    int role = tid >> 7;          // 0..3
    int t7 = tid & 127;
    int r0 = (t7 >> 4) << 3;      // i/n tile base: 0,8,...,56
    int h0 = (t7 & 15) << 2;      // h base: 0,4,...,60

    // staging coords
    int vii = tid & 63, vng = tid >> 6;   // V prefetch: 8 n per thread (8 groups)
    int n0v = vng << 3;

    const float* ub = u + (size_t)b * LSEQ * HD + habs;
    float*       yb = y + (size_t)b * LSEQ * HD + habs;

    // ---- zero X ping, stage chunk 0 (synchronous) ----
    for (int e = tid; e < 4096; e += 512) Xb0[e] = 0.f;
    for (int f = tid; f < 1024; f += 512) {
        int j = f >> 4, q = f & 15;
        ((float4*)Us0)[(j << 4) + q] = __ldg((const float4*)(ub + (size_t)j * HD) + q);
        ((float4*)Ws0)[f] = __ldg((const float4*)d_W + f);
    }
    {
        const float* Vrow = d_V + (size_t)vii * 64 + n0v;
#pragma unroll
        for (int q2 = 0; q2 < 2; q2++) {
            float4 v = *(const float4*)(Vrow + (q2 << 2));
            int nn = n0v + (q2 << 2);
            Vt0[(nn + 0) * 64 + vii] = v.x;
            Vt0[(nn + 1) * 64 + vii] = v.y;
            Vt0[(nn + 2) * 64 + vii] = v.z;
            Vt0[(nn + 3) * 64 + vii] = v.w;
        }
    }
    __syncthreads();

    // ---- one-time Toeplitz: Tz[j][i] = dot(v_i, w_j) masked i>=j ----
    {
        int jj = tid >> 3;
        int i0t = (tid & 7) << 3;
        float ta[8];
#pragma unroll
        for (int q = 0; q < 8; q++) ta[q] = 0.f;
#pragma unroll 4
        for (int n = 0; n < 64; n++) {
            float w = Ws0[jj * 64 + n];
            const float* vr = Vt0 + n * 64 + i0t;
            float4 v0 = *(const float4*)(vr);
            float4 v1 = *(const float4*)(vr + 4);
#pragma unroll
            for (int q = 0; q < 4; q++) {
                ta[q]     = fmaf(w, (&v0.x)[q], ta[q]);
                ta[4 + q] = fmaf(w, (&v1.x)[q], ta[4 + q]);
            }
        }
#pragma unroll
        for (int q = 0; q < 8; q++)
            Tz[jj * 64 + i0t + q] = (i0t + q >= jj) ? ta[q] : 0.f;
    }
    __syncthreads();

    float* Xc = Xb0;
    float* Xn = Xb1;

    for (int c = 0; c < 32; c++) {
        int p = c & 1;
        int tb = c << 6;
        const float* Uc = p ? Us1 : Us0;
        const float* Wc = p ? Ws1 : Ws0;
        const float* Vc = p ? Vt1 : Vt0;
        uint32_t uAlt = smem_u32 + (p ? 0u : 4096u * 4u);
        uint32_t wAlt = smem_u32 + (p ? 8192u * 4u : 12288u * 4u);
        float*   vAlt = p ? Vt0 : Vt1;

        // ---- async prefetch next chunk: U and W via cp.async ----
        float4 pv[2];
        if (c < 31) {
            int tbn = tb + 64;
#pragma unroll
            for (int it = 0; it < 2; it++) {
                int f = (it << 9) + tid;
                int j = f >> 4, q = f & 15;
                cpa16(uAlt + (uint32_t)((j << 6) + (q << 2)) * 4u,
                      ub + (size_t)(tbn + j) * HD + (q << 2));
                cpa16(wAlt + (uint32_t)((j << 6) + (q << 2)) * 4u,
                      d_W + (size_t)(tbn + j) * 64 + (q << 2));
            }
            cpa_commit();
            const float* Vrow = d_V + (size_t)(tbn + vii) * 64 + n0v;
#pragma unroll
            for (int q2 = 0; q2 < 2; q2++) pv[q2] = *(const float4*)(Vrow + (q2 << 2));
        }

        // ---- compute role partials ----
        uint64_t acc[8][2];
#pragma unroll
        for (int ai = 0; ai < 8; ai++) { acc[ai][0] = 0ull; acc[ai][1] = 0ull; }

        if (role == 0) {
#pragma unroll 4
            for (int n = 0; n < 64; n++) g8x4(acc, Vc, Xc, n, r0, h0);
#pragma unroll
            for (int ai = 0; ai < 8; ai++) {
                ulonglong2 o; o.x = acc[ai][0]; o.y = acc[ai][1];
                *(ulonglong2*)(Yb_ + (r0 + ai) * 64 + h0) = o;
            }
        } else if (role == 1) {
#pragma unroll 4
            for (int j = 0; j < 64; j++) g8x4(acc, Tz, Uc, j, r0, h0);
#pragma unroll
            for (int ai = 0; ai < 8; ai++) {
                ulonglong2 uv = *(const ulonglong2*)(Uc + (r0 + ai) * 64 + h0);
                fma2(acc[ai][0], dv2, uv.x);
                fma2(acc[ai][1], dv2, uv.y);
            }
        } else if (role == 2) {
#pragma unroll 4
            for (int j = 0; j < 32; j++) g8x4(acc, Wc, Uc, j, r0, h0);
#pragma unroll
            for (int ai = 0; ai < 8; ai++) {
                ulonglong2 xv = *(const ulonglong2*)(Xc + (r0 + ai) * 64 + h0);
                add2(acc[ai][0], xv.x);
                add2(acc[ai][1], xv.y);
                ulonglong2 o; o.x = acc[ai][0]; o.y = acc[ai][1];
                *(ulonglong2*)(Xn + (r0 + ai) * 64 + h0) = o;
            }
        } else {
#pragma unroll 4
            for (int j = 32; j < 64; j++) g8x4(acc, Wc, Uc, j, r0, h0);
        }

        // ---- V prefetch STS into alt buffer (all threads) ----
        if (c < 31) {
#pragma unroll
            for (int q2 = 0; q2 < 2; q2++) {
                int nn = n0v + (q2 << 2);
                vAlt[(nn + 0) * 64 + vii] = pv[q2].x;
                vAlt[(nn + 1) * 64 + vii] = pv[q2].y;
                vAlt[(nn + 2) * 64 + vii] = pv[q2].z;
                vAlt[(nn + 3) * 64 + vii] = pv[q2].w;
            }
        }
        __syncthreads();   // Yb + Xn(partial A) visible

        if (role == 1) {
#pragma unroll
            for (int ai = 0; ai < 8; ai++) {
                ulonglong2 p1 = *(const ulonglong2*)(Yb_ + (r0 + ai) * 64 + h0);
                add2(acc[ai][0], p1.x);
                add2(acc[ai][1], p1.y);
                ulonglong2 o; o.x = acc[ai][0]; o.y = acc[ai][1];
                *(ulonglong2*)(yb + (size_t)(tb + r0 + ai) * HD + h0) = o;
            }
        } else if (role == 3) {
#pragma unroll
            for (int ai = 0; ai < 8; ai++) {
                float* xrow = Xn + (r0 + ai) * 64 + h0;
                ulonglong2 xv = *(const ulonglong2*)xrow;
                add2(acc[ai][0], xv.x);
                add2(acc[ai][1], xv.y);
                ulonglong2 o; o.x = acc[ai][0]; o.y = acc[ai][1];
                *(ulonglong2*)xrow = o;
            }
        }

        cpa_wait0();
        __syncthreads();   // Xn final, new tiles landed

        float* t = Xc; Xc = Xn; Xn = t;
    }
}

extern "C" void kernel_launch(void* const* d_in, const int* in_sizes, int n_in,
                              void* d_out, int out_size) {
    const float* u      = (const float*)d_in[0];
    const float* B_ssm  = (const float*)d_in[1];
    const float* C_ssm  = (const float*)d_in[2];
    const float* D_skip = (const float*)d_in[3];
    const float* log_dt = (const float*)d_in[4];
    float* y = (float*)d_out;

    cudaFuncSetAttribute(setup_kernel, cudaFuncAttributeMaxDynamicSharedMemorySize, 114688);
    cudaFuncSetAttribute(chunk_kernel, cudaFuncAttributeMaxDynamicSharedMemorySize, 98304);
    cudaFuncSetAttribute(main_kernel,  cudaFuncAttributeMaxDynamicSharedMemorySize, 163840);

    setup_kernel<<<1, 256, 114688>>>(B_ssm, log_dt);
    stageA_kernel<<<2, 256>>>(C_ssm);
    chunk_kernel<<<32, 256, 98304>>>();
    main_kernel<<<BSZ * 8, 512, 163840>>>(u, D_skip, y);
}